// round 2
// baseline (speedup 1.0000x reference)
#include <cuda_runtime.h>
#include <math.h>

#define NE 160000
#define NN 10000
#define CC 64
#define HH 512
#define TLE 32          // edges per block in layer kernel
#define PI_F 3.14159265358979323846f

// ---- scratch (static __device__, no allocation) ----
__device__ float g_x[NE * CC];        // latent per edge
__device__ float g_u[NE * 3];         // unit vectors
__device__ float g_env[NE];           // cutoff envelope
__device__ float g_V[NE * CC * 3];    // equivariant features
__device__ float g_rho0[NN * CC];     // scalar density
__device__ float g_rho1[NN * CC * 3]; // vector density

__device__ __forceinline__ float silu_f(float v) {
    return v / (1.f + __expf(-v));
}

// ============================================================
// K1: geometry + radial basis + 12->512->64 embed MLP
// 16 edges / block, 256 threads
// ============================================================
__global__ __launch_bounds__(256) void k_embed(
    const float* __restrict__ pos,
    const int* __restrict__ species,
    const int* __restrict__ senders,
    const int* __restrict__ receivers,
    const float* __restrict__ W1,     // [12,512]
    const float* __restrict__ W2)     // [512,64]
{
    __shared__ float s_feat[16][12];
    __shared__ float s_hidden[16 * HH];
    __shared__ float s_env[16];
    const int tid = threadIdx.x;
    const int e0 = blockIdx.x * 16;

    if (tid < 16) {
        int e = e0 + tid;
        int sn = senders[e], rc = receivers[e];
        float rx = pos[rc * 3 + 0] - pos[sn * 3 + 0];
        float ry = pos[rc * 3 + 1] - pos[sn * 3 + 1];
        float rz = pos[rc * 3 + 2] - pos[sn * 3 + 2];
        float d = sqrtf(rx * rx + ry * ry + rz * rz);
        float ds = fmaxf(d, 1e-6f);
        float inv = 1.f / ds;
        g_u[e * 3 + 0] = rx * inv;
        g_u[e * 3 + 1] = ry * inv;
        g_u[e * 3 + 2] = rz * inv;
        float xc = d * 0.5f;               // d / CUT, CUT=2
        float env = 0.f;
        if (xc < 1.f) { float t = 1.f - xc * xc; env = t * t; }
        g_env[e] = env;
        s_env[tid] = env;
        float pref = env * inv;            // sqrt(2/CUT)=1 for CUT=2
        float ang = PI_F * xc;
        #pragma unroll
        for (int n = 1; n <= 8; n++)
            s_feat[tid][n - 1] = pref * __sinf((float)n * ang);
        float ssn = (species[sn] == 1) ? 1.f : 0.f;
        float src = (species[rc] == 1) ? 1.f : 0.f;
        s_feat[tid][8]  = 1.f - ssn;
        s_feat[tid][9]  = ssn;
        s_feat[tid][10] = 1.f - src;
        s_feat[tid][11] = src;
    }
    __syncthreads();

    // phase A: hidden = silu(feat @ W1)
    #pragma unroll
    for (int j = 0; j < 2; j++) {
        int h = tid + 256 * j;
        float w1r[12];
        #pragma unroll
        for (int k = 0; k < 12; k++) w1r[k] = W1[k * HH + h];
        #pragma unroll 4
        for (int i = 0; i < 16; i++) {
            float acc = 0.f;
            #pragma unroll
            for (int k = 0; k < 12; k++) acc += s_feat[i][k] * w1r[k];
            s_hidden[i * HH + h] = silu_f(acc);
        }
    }
    __syncthreads();

    // phase B: x = (hidden @ W2) * env
    const int c  = tid & 63;
    const int i0 = (tid >> 6) * 4;
    float acc[4] = {0.f, 0.f, 0.f, 0.f};
    for (int h = 0; h < HH; h++) {
        float w = W2[h * CC + c];
        #pragma unroll
        for (int j = 0; j < 4; j++) acc[j] += s_hidden[(i0 + j) * HH + h] * w;
    }
    #pragma unroll
    for (int j = 0; j < 4; j++)
        g_x[(e0 + i0 + j) * CC + c] = acc[j] * s_env[i0 + j];
}

// ============================================================
// K2: V = (x @ W_v) outer u     4 edges / block
// ============================================================
__global__ __launch_bounds__(256) void k_vinit(const float* __restrict__ Wv)
{
    __shared__ float s_w[CC * CC];
    __shared__ float s_x[4 * CC];
    const int tid = threadIdx.x;
    const int e0 = blockIdx.x * 4;
    for (int idx = tid; idx < CC * CC; idx += 256) s_w[idx] = Wv[idx];
    s_x[tid] = g_x[e0 * CC + tid];
    __syncthreads();
    int i = tid >> 6, c = tid & 63;
    float acc = 0.f;
    #pragma unroll 8
    for (int k = 0; k < CC; k++) acc += s_x[i * CC + k] * s_w[k * CC + c];
    int e = e0 + i;
    float ux = g_u[e * 3 + 0], uy = g_u[e * 3 + 1], uz = g_u[e * 3 + 2];
    int vb = (e * CC + c) * 3;
    g_V[vb + 0] = acc * ux;
    g_V[vb + 1] = acc * uy;
    g_V[vb + 2] = acc * uz;
}

// ============================================================
// zero kernels
// ============================================================
__global__ void k_zero_rho() {
    int idx = blockIdx.x * 256 + threadIdx.x;
    if (idx < NN * CC)     g_rho0[idx] = 0.f;
    if (idx < NN * CC * 3) g_rho1[idx] = 0.f;
}
__global__ void k_zero_out(float* __restrict__ out) {
    int idx = blockIdx.x * 256 + threadIdx.x;
    if (idx < NN) out[idx] = 0.f;
}

// ============================================================
// K3: w_e = x @ W_env[l]; scatter to rho0/rho1 by senders (atomic)
// 4 edges / block
// ============================================================
__global__ __launch_bounds__(256) void k_scatter(
    const float* __restrict__ Wenv,
    const int* __restrict__ senders)
{
    __shared__ float s_w[CC * CC];
    __shared__ float s_x[4 * CC];
    const int tid = threadIdx.x;
    const int e0 = blockIdx.x * 4;
    for (int idx = tid; idx < CC * CC; idx += 256) s_w[idx] = Wenv[idx];
    s_x[tid] = g_x[e0 * CC + tid];
    __syncthreads();
    int i = tid >> 6, c = tid & 63;
    float acc = 0.f;
    #pragma unroll 8
    for (int k = 0; k < CC; k++) acc += s_x[i * CC + k] * s_w[k * CC + c];
    int e = e0 + i;
    acc *= (1.f / 3.0f);                   // /AVG folded into scatter
    int sn = senders[e];
    float ux = g_u[e * 3 + 0], uy = g_u[e * 3 + 1], uz = g_u[e * 3 + 2];
    atomicAdd(&g_rho0[sn * CC + c], acc);
    int rb = (sn * CC + c) * 3;
    atomicAdd(&g_rho1[rb + 0], acc * ux);
    atomicAdd(&g_rho1[rb + 1], acc * uy);
    atomicAdd(&g_rho1[rb + 2], acc * uz);
}

// ============================================================
// K4: full layer update — gather, TP, 192->512->64 MLP, mix, V update
// 32 edges / block, 256 threads, 88 KB dynamic smem
// ============================================================
__global__ __launch_bounds__(256) void k_layer(
    const float* __restrict__ W1,   // [192,512]
    const float* __restrict__ W2,   // [512,64]
    const float* __restrict__ Wm,   // [64,128]
    const int* __restrict__ senders)
{
    extern __shared__ float sm[];
    float* s_lat    = sm;                 // [32][192]
    float* s_hidden = sm + TLE * 192;     // [32][512]  (aliased as mix later)
    __shared__ int   s_send[TLE];
    __shared__ float s_env[TLE];

    const int tid = threadIdx.x;
    const int e0 = blockIdx.x * TLE;

    if (tid < TLE) {
        int e = e0 + tid;
        s_send[tid] = senders[e];
        s_env[tid] = g_env[e];
    }
    __syncthreads();

    // ---- build lat_in = [x | tp_scal | rho0_e] ----
    #pragma unroll
    for (int t = 0; t < (TLE * CC) / 256; t++) {
        int idx = tid + 256 * t;
        int i = idx >> 6, c = idx & 63;
        int e = e0 + i, sn = s_send[i];
        float xv = g_x[e * CC + c];
        float r0 = g_rho0[sn * CC + c];
        int rb = (sn * CC + c) * 3;
        float r1x = g_rho1[rb], r1y = g_rho1[rb + 1], r1z = g_rho1[rb + 2];
        int vb = (e * CC + c) * 3;
        float Vx = g_V[vb], Vy = g_V[vb + 1], Vz = g_V[vb + 2];
        s_lat[i * 192 + c]        = xv;
        s_lat[i * 192 + 64 + c]   = Vx * r1x + Vy * r1y + Vz * r1z;
        s_lat[i * 192 + 128 + c]  = r0;
    }
    __syncthreads();

    // ---- phase 1: hidden = silu(lat @ W1), 4x4 register tiles ----
    {
        const int hg  = tid & 127;
        const int h0  = hg * 4;
        const int ig0 = (tid >> 7) * 16;
        for (int sub = 0; sub < 4; sub++) {
            int i0 = ig0 + sub * 4;
            float a00=0,a01=0,a02=0,a03=0, a10=0,a11=0,a12=0,a13=0;
            float a20=0,a21=0,a22=0,a23=0, a30=0,a31=0,a32=0,a33=0;
            for (int k = 0; k < 192; k++) {
                float4 w = *reinterpret_cast<const float4*>(&W1[k * HH + h0]);
                float l0 = s_lat[(i0 + 0) * 192 + k];
                float l1 = s_lat[(i0 + 1) * 192 + k];
                float l2 = s_lat[(i0 + 2) * 192 + k];
                float l3 = s_lat[(i0 + 3) * 192 + k];
                a00 += l0 * w.x; a01 += l0 * w.y; a02 += l0 * w.z; a03 += l0 * w.w;
                a10 += l1 * w.x; a11 += l1 * w.y; a12 += l1 * w.z; a13 += l1 * w.w;
                a20 += l2 * w.x; a21 += l2 * w.y; a22 += l2 * w.z; a23 += l2 * w.w;
                a30 += l3 * w.x; a31 += l3 * w.y; a32 += l3 * w.z; a33 += l3 * w.w;
            }
            float4 hv;
            hv.x = silu_f(a00); hv.y = silu_f(a01); hv.z = silu_f(a02); hv.w = silu_f(a03);
            *reinterpret_cast<float4*>(&s_hidden[(i0 + 0) * HH + h0]) = hv;
            hv.x = silu_f(a10); hv.y = silu_f(a11); hv.z = silu_f(a12); hv.w = silu_f(a13);
            *reinterpret_cast<float4*>(&s_hidden[(i0 + 1) * HH + h0]) = hv;
            hv.x = silu_f(a20); hv.y = silu_f(a21); hv.z = silu_f(a22); hv.w = silu_f(a23);
            *reinterpret_cast<float4*>(&s_hidden[(i0 + 2) * HH + h0]) = hv;
            hv.x = silu_f(a30); hv.y = silu_f(a31); hv.z = silu_f(a32); hv.w = silu_f(a33);
            *reinterpret_cast<float4*>(&s_hidden[(i0 + 3) * HH + h0]) = hv;
        }
    }
    __syncthreads();

    // ---- phase 2: dx = hidden @ W2; x = (x + dx*env)/sqrt(2) ----
    {
        const int c  = tid & 63;
        const int i0 = (tid >> 6) * 8;
        float acc[8] = {0, 0, 0, 0, 0, 0, 0, 0};
        for (int h = 0; h < HH; h++) {
            float w = W2[h * CC + c];
            #pragma unroll
            for (int j = 0; j < 8; j++) acc[j] += s_hidden[(i0 + j) * HH + h] * w;
        }
        const float inv_s2 = 0.70710678118654752f;
        #pragma unroll
        for (int j = 0; j < 8; j++) {
            int i = i0 + j;
            float xn = (s_lat[i * 192 + c] + acc[j] * s_env[i]) * inv_s2;
            s_lat[i * 192 + c] = xn;
            g_x[(e0 + i) * CC + c] = xn;
        }
    }
    __syncthreads();

    // ---- phase 3a: mix = x_new @ Wm  (into s_hidden region, [32][128]) ----
    float* s_mix = s_hidden;
    {
        const int m  = tid & 127;
        const int ig = (tid >> 7) * 16;
        for (int j = 0; j < 16; j++) {
            int i = ig + j;
            float acc = 0.f;
            #pragma unroll 8
            for (int k = 0; k < CC; k++) acc += s_lat[i * 192 + k] * Wm[k * 128 + m];
            s_mix[i * 128 + m] = acc;
        }
    }
    __syncthreads();

    // ---- phase 3b: V = mix1 * (V * rho0) + mix2 * cross(V, rho1) ----
    #pragma unroll
    for (int t = 0; t < (TLE * CC) / 256; t++) {
        int idx = tid + 256 * t;
        int i = idx >> 6, c = idx & 63;
        int e = e0 + i, sn = s_send[i];
        int vb = (e * CC + c) * 3;
        float Vx = g_V[vb], Vy = g_V[vb + 1], Vz = g_V[vb + 2];
        int rb = (sn * CC + c) * 3;
        float r1x = g_rho1[rb], r1y = g_rho1[rb + 1], r1z = g_rho1[rb + 2];
        float r0 = s_lat[i * 192 + 128 + c];
        float m1 = s_mix[i * 128 + c];
        float m2 = s_mix[i * 128 + 64 + c];
        float cx = Vy * r1z - Vz * r1y;
        float cy = Vz * r1x - Vx * r1z;
        float cz = Vx * r1y - Vy * r1x;
        g_V[vb + 0] = m1 * Vx * r0 + m2 * cx;
        g_V[vb + 1] = m1 * Vy * r0 + m2 * cy;
        g_V[vb + 2] = m1 * Vz * r0 + m2 * cz;
    }
}

// ============================================================
// K5: e_edge = (x @ W_out)*env -> scatter to receivers (warp per edge)
// ============================================================
__global__ __launch_bounds__(256) void k_out(
    const float* __restrict__ Wo,
    const int* __restrict__ receivers,
    float* __restrict__ out)
{
    int w = threadIdx.x >> 5, lane = threadIdx.x & 31;
    int e = blockIdx.x * 8 + w;
    float p = g_x[e * CC + lane] * Wo[lane]
            + g_x[e * CC + 32 + lane] * Wo[32 + lane];
    #pragma unroll
    for (int off = 16; off; off >>= 1) p += __shfl_xor_sync(0xffffffff, p, off);
    if (lane == 0) {
        float v = p * g_env[e] * (1.f / 3.0f);
        atomicAdd(&out[receivers[e]], v);
    }
}

// ============================================================
extern "C" void kernel_launch(void* const* d_in, const int* in_sizes, int n_in,
                              void* d_out, int out_size)
{
    const float* pos     = (const float*)d_in[0];
    const float* W_emb1  = (const float*)d_in[1];
    const float* W_emb2  = (const float*)d_in[2];
    const float* W_v     = (const float*)d_in[3];
    const float* W_env   = (const float*)d_in[4];
    const float* W_lat1  = (const float*)d_in[5];
    const float* W_lat2  = (const float*)d_in[6];
    const float* W_mix   = (const float*)d_in[7];
    const float* W_out   = (const float*)d_in[8];
    const int*   species = (const int*)d_in[9];
    const int*   senders = (const int*)d_in[10];
    const int*   recv    = (const int*)d_in[11];
    float* out = (float*)d_out;

    const int smem_layer = (TLE * 192 + TLE * HH) * sizeof(float);  // 90112 B
    cudaFuncSetAttribute(k_layer, cudaFuncAttributeMaxDynamicSharedMemorySize, smem_layer);

    k_zero_out<<<(NN + 255) / 256, 256>>>(out);
    k_embed<<<NE / 16, 256>>>(pos, species, senders, recv, W_emb1, W_emb2);
    k_vinit<<<NE / 4, 256>>>(W_v);

    for (int l = 0; l < 2; l++) {
        k_zero_rho<<<(NN * CC * 3 + 255) / 256, 256>>>();
        k_scatter<<<NE / 4, 256>>>(W_env + l * CC * CC, senders);
        k_layer<<<NE / TLE, 256, smem_layer>>>(
            W_lat1 + l * 192 * HH,
            W_lat2 + l * HH * CC,
            W_mix  + l * CC * 128,
            senders);
    }
    k_out<<<NE / 8, 256>>>(W_out, recv, out);
}